// round 14
// baseline (speedup 1.0000x reference)
#include <cuda_runtime.h>

#define N_MAX 100000
#define SLOT 64

// ---------------- scratch (zero-initialized at module load; k_final
// restores g_deg/g_indeg to zero after use -> zero-on-entry invariant) ------
__device__ __align__(16) float g_featn[N_MAX * 8];
__device__ __align__(16) float g_U[N_MAX * 64];      // gate-interleaved [i][j(16)][gate(4)]
__device__ __align__(16) float g_h0[N_MAX * 32];     // a_i * [featn(8) | h(16) | 0(8)]
__device__ float g_deg[N_MAX];
__device__ int   g_indeg[N_MAX];
__device__ __align__(16) int2 g_csr[N_MAX * SLOT];   // packed (src, ew bits)
__device__ __align__(16) float g_out0[N_MAX * 64];   // a_i * leaky(...)
__device__ __align__(16) float g_m2[N_MAX * 32];     // a_i * (y @ W2)

// ---------------- activations ----------------
__device__ __forceinline__ float fsig(float x) {
    return __fdividef(1.0f, 1.0f + __expf(-x));
}
__device__ __forceinline__ float ftanh_(float x) {
    return 1.0f - __fdividef(2.0f, __expf(2.0f * x) + 1.0f);
}
__device__ __forceinline__ float lrelu(float v) { return v > 0.0f ? v : 0.01f * v; }

// ---------------- fused pre-pass: norm+U blocks || edge blocks -------------
__global__ void __launch_bounds__(256) k_pre(const float* __restrict__ feat,
                                             const float* __restrict__ Wih,
                                             const float* __restrict__ bih,
                                             const float* __restrict__ bhh,
                                             const int* __restrict__ esrc,
                                             const int* __restrict__ edst,
                                             const float* __restrict__ ew,
                                             int n, int E, int nbN) {
    int tid = threadIdx.x;
    if ((int)blockIdx.x < nbN) {
        // ---- norm + U role ----
        __shared__ __align__(16) float sWI[512];  // [j(16)][k(8)][gate(4)]
        __shared__ __align__(16) float sB[64];
        for (int idx = tid; idx < 512; idx += 256) {
            int g = idx & 3, k = (idx >> 2) & 7, j = idx >> 5;
            sWI[idx] = Wih[(j + 16 * g) * 8 + k];
        }
        if (tid < 64) {
            int g = tid & 3, j = tid >> 2;
            sB[tid] = bih[j + 16 * g] + bhh[j + 16 * g];
        }
        __syncthreads();
        int i = blockIdx.x * 256 + tid;
        if (i >= n) return;

        const float4* f4 = reinterpret_cast<const float4*>(feat + (size_t)i * 8);
        float4 a = f4[0], b = f4[1];
        float v[8] = {a.x, a.y, a.z, a.w, b.x, b.y, b.z, b.w};
        float s = 0.0f;
#pragma unroll
        for (int k = 0; k < 8; k++) s += v[k];
        float inv = __fdividef(1.0f, s);
#pragma unroll
        for (int k = 0; k < 8; k++) v[k] *= inv;
        float4* o4 = reinterpret_cast<float4*>(g_featn + (size_t)i * 8);
        o4[0] = make_float4(v[0], v[1], v[2], v[3]);
        o4[1] = make_float4(v[4], v[5], v[6], v[7]);

        const float4* W4 = reinterpret_cast<const float4*>(sWI);
        const float4* B4 = reinterpret_cast<const float4*>(sB);
        float4* u4 = reinterpret_cast<float4*>(g_U + (size_t)i * 64);
#pragma unroll
        for (int j = 0; j < 16; j++) {
            float4 acc = B4[j];
#pragma unroll
            for (int k = 0; k < 8; k++) {
                float4 w = W4[j * 8 + k];
                acc.x += v[k] * w.x; acc.y += v[k] * w.y;
                acc.z += v[k] * w.z; acc.w += v[k] * w.w;
            }
            u4[j] = acc;
        }
    } else {
        // ---- edge role: 4 edges/thread, run-grouped deg atomics ----
        int e0 = ((blockIdx.x - nbN) * 256 + tid) * 4;
        if (e0 >= E) return;
        if (e0 + 4 <= E) {
            int4 s4 = *reinterpret_cast<const int4*>(esrc + e0);
            int4 d4 = *reinterpret_cast<const int4*>(edst + e0);
            float4 w4 = *reinterpret_cast<const float4*>(ew + e0);

            int cur = s4.x;
            float acc = w4.x;
            if (s4.y == cur) acc += w4.y;
            else { atomicAdd(&g_deg[cur], acc); cur = s4.y; acc = w4.y; }
            if (s4.z == cur) acc += w4.z;
            else { atomicAdd(&g_deg[cur], acc); cur = s4.z; acc = w4.z; }
            if (s4.w == cur) acc += w4.w;
            else { atomicAdd(&g_deg[cur], acc); cur = s4.w; acc = w4.w; }
            atomicAdd(&g_deg[cur], acc);

            int p;
            p = atomicAdd(&g_indeg[d4.x], 1);
            if (p < SLOT) g_csr[(size_t)d4.x * SLOT + p] = make_int2(s4.x, __float_as_int(w4.x));
            p = atomicAdd(&g_indeg[d4.y], 1);
            if (p < SLOT) g_csr[(size_t)d4.y * SLOT + p] = make_int2(s4.y, __float_as_int(w4.y));
            p = atomicAdd(&g_indeg[d4.z], 1);
            if (p < SLOT) g_csr[(size_t)d4.z * SLOT + p] = make_int2(s4.z, __float_as_int(w4.z));
            p = atomicAdd(&g_indeg[d4.w], 1);
            if (p < SLOT) g_csr[(size_t)d4.w * SLOT + p] = make_int2(s4.w, __float_as_int(w4.w));
        } else {
            for (int e = e0; e < E; e++) {
                int s = esrc[e];
                float w = ew[e];
                atomicAdd(&g_deg[s], w);
                int d = edst[e];
                int p = atomicAdd(&g_indeg[d], 1);
                if (p < SLOT) g_csr[(size_t)d * SLOT + p] = make_int2(s, __float_as_int(w));
            }
        }
    }
}

// ---------------- LSTM: SMEM window staging + split gate chains -----------
#define UROWS 133          // 128 + 5 halo
#define USTRIDE 68         // floats per staged row (16B aligned, conflict-free)
__global__ void __launch_bounds__(128) k_lstm(const float* __restrict__ Whh,
                                              const float* __restrict__ bih,
                                              const float* __restrict__ bhh, int n) {
    __shared__ __align__(16) float sWhh[1024];  // [(j*16+k)][gate(4)]
    __shared__ __align__(16) float sB[64];
    __shared__ __align__(16) float sU[UROWS * USTRIDE];  // ~36 KB
    int tid = threadIdx.x;
    for (int idx = tid; idx < 1024; idx += 128) {
        int g = idx & 3, k = (idx >> 2) & 15, j = idx >> 6;
        sWhh[idx] = Whh[(j + 16 * g) * 16 + k];
    }
    if (tid < 64) {
        int g = tid & 3, j = tid >> 2;
        sB[tid] = bih[j + 16 * g] + bhh[j + 16 * g];
    }

    int gbase = blockIdx.x * 128 - 5;
    const float4* U4 = reinterpret_cast<const float4*>(g_U);
    for (int idx = tid; idx < UROWS * 16; idx += 128) {
        int r = idx >> 4, c = idx & 15;
        int gr = gbase + r;
        float4 val = make_float4(0.f, 0.f, 0.f, 0.f);
        if (gr >= 0 && gr < n) val = U4[(size_t)gr * 16 + c];
        *reinterpret_cast<float4*>(sU + r * USTRIDE + c * 4) = val;
    }
    __syncthreads();

    int i = blockIdx.x * 128 + tid;
    if (i >= n) return;

    const float4* W4 = reinterpret_cast<const float4*>(sWhh);
    const float4* B4 = reinterpret_cast<const float4*>(sB);

    float h[16], c[16];
#pragma unroll
    for (int k = 0; k < 16; k++) { h[k] = 0.0f; c[k] = 0.0f; }

    int vmax = (i < 5) ? i : 5;
    int base = (i >= 5) ? (i - 5) : 0;

#pragma unroll 1
    for (int t = 0; t < 5; t++) {
        int gr = base + t;
        const float4* up = (t < vmax)
            ? reinterpret_cast<const float4*>(sU + (gr - gbase) * USTRIDE)
            : B4;
        float hn[16];
#pragma unroll 1
        for (int j = 0; j < 16; j++) {
            float4 u = up[j];
            float giA = u.x, gfA = u.y, ggA = u.z, goA = u.w;
            float giB = 0.f, gfB = 0.f, ggB = 0.f, goB = 0.f;
#pragma unroll
            for (int k = 0; k < 8; k++) {
                float4 w = W4[j * 16 + k];
                float hk = h[k];
                giA += hk * w.x; gfA += hk * w.y; ggA += hk * w.z; goA += hk * w.w;
            }
#pragma unroll
            for (int k = 8; k < 16; k++) {
                float4 w = W4[j * 16 + k];
                float hk = h[k];
                giB += hk * w.x; gfB += hk * w.y; ggB += hk * w.z; goB += hk * w.w;
            }
            float gi = giA + giB, gf = gfA + gfB, gg = ggA + ggB, go = goA + goB;
            float cj = fsig(gf) * c[j] + fsig(gi) * ftanh_(gg);
            c[j] = cj;
            hn[j] = fsig(go) * ftanh_(cj);
        }
#pragma unroll
        for (int j = 0; j < 16; j++) h[j] = hn[j];
    }

    float ai = rsqrtf(g_deg[i]);
    float4* o4 = reinterpret_cast<float4*>(g_h0 + (size_t)i * 32);
    const float4* f4 = reinterpret_cast<const float4*>(g_featn + (size_t)i * 8);
    float4 fa = f4[0], fb = f4[1];
    o4[0] = make_float4(fa.x * ai, fa.y * ai, fa.z * ai, fa.w * ai);
    o4[1] = make_float4(fb.x * ai, fb.y * ai, fb.z * ai, fb.w * ai);
    o4[2] = make_float4(h[0] * ai, h[1] * ai, h[2] * ai, h[3] * ai);
    o4[3] = make_float4(h[4] * ai, h[5] * ai, h[6] * ai, h[7] * ai);
    o4[4] = make_float4(h[8] * ai, h[9] * ai, h[10] * ai, h[11] * ai);
    o4[5] = make_float4(h[12] * ai, h[13] * ai, h[14] * ai, h[15] * ai);
    o4[6] = make_float4(0.f, 0.f, 0.f, 0.f);
    o4[7] = make_float4(0.f, 0.f, 0.f, 0.f);
}

// ---------------- layer 0: agg(h0', 24) -> @W0+b0 -> leaky -> *a_i ----------
__global__ void __launch_bounds__(256) k_l0(const float* __restrict__ W0,
                                            const float* __restrict__ b0, int n) {
    __shared__ float sW[24 * 64];
    __shared__ float sBv[64];
    int tid = threadIdx.x;
    for (int idx = tid; idx < 24 * 64; idx += 256) sW[idx] = W0[idx];
    if (tid < 64) sBv[tid] = b0[tid];
    __syncthreads();

    const unsigned full = 0xffffffffu;
    int wp = (blockIdx.x * 256 + tid) >> 5;
    int lane = tid & 31;
    if (wp >= n) return;
    int cnt = g_indeg[wp];
    if (cnt > SLOT) cnt = SLOT;
    const int2* cs = g_csr + (size_t)wp * SLOT;
    int2 pkA = make_int2(0, 0);
    if (lane < cnt) pkA = cs[lane];
    int q = lane >> 3, l = lane & 7;
    const float4* S4 = reinterpret_cast<const float4*>(g_h0);
    float4 a0 = make_float4(0.f, 0.f, 0.f, 0.f);
    float4 a1 = make_float4(0.f, 0.f, 0.f, 0.f);
    int c1 = cnt < 32 ? cnt : 32;
    // dual accumulators; e<=24 so lane indices e+4+q <= 31 (no shfl wrap);
    // slots >= cnt carry zero weight -> harmless
#pragma unroll 2
    for (int e = 0; e < c1; e += 8) {
        int eA = e + q;
        int sA = __shfl_sync(full, pkA.x, eA);
        float wA = __int_as_float(__shfl_sync(full, pkA.y, eA));
        float4 vA = S4[(size_t)sA * 8 + l];
        a0.x += wA * vA.x; a0.y += wA * vA.y; a0.z += wA * vA.z; a0.w += wA * vA.w;
        int eB = e + 4 + q;
        int sB_ = __shfl_sync(full, pkA.x, eB);
        float wB = __int_as_float(__shfl_sync(full, pkA.y, eB));
        float4 vB = S4[(size_t)sB_ * 8 + l];
        a1.x += wB * vB.x; a1.y += wB * vB.y; a1.z += wB * vB.z; a1.w += wB * vB.w;
    }
    for (int e = 32; e < cnt; e += 4) {      // rare tail
        int ee = e + q;
        bool ok = ee < cnt;
        int2 pk = ok ? cs[ee] : make_int2(0, 0);
        float wgt = __int_as_float(pk.y);
        float4 v = S4[(size_t)pk.x * 8 + l];
        a0.x += wgt * v.x; a0.y += wgt * v.y; a0.z += wgt * v.z; a0.w += wgt * v.w;
    }
    float4 acc = make_float4(a0.x + a1.x, a0.y + a1.y, a0.z + a1.z, a0.w + a1.w);
#pragma unroll
    for (int m = 8; m <= 16; m <<= 1) {
        acc.x += __shfl_xor_sync(full, acc.x, m);
        acc.y += __shfl_xor_sync(full, acc.y, m);
        acc.z += __shfl_xor_sync(full, acc.z, m);
        acc.w += __shfl_xor_sync(full, acc.w, m);
    }
    float ai = rsqrtf(g_deg[wp]);
    acc.x *= ai; acc.y *= ai; acc.z *= ai; acc.w *= ai;

    float t[24];
#pragma unroll
    for (int k = 0; k < 24; k++) {
        float src = ((k & 3) == 0) ? acc.x : ((k & 3) == 1) ? acc.y : ((k & 3) == 2) ? acc.z : acc.w;
        t[k] = __shfl_sync(full, src, k >> 2);
    }
    int j = lane;
    float o0 = sBv[j], o1 = sBv[j + 32];
#pragma unroll
    for (int k = 0; k < 24; k++) {
        o0 += t[k] * sW[k * 64 + j];
        o1 += t[k] * sW[k * 64 + j + 32];
    }
    o0 = lrelu(o0) * ai;
    o1 = lrelu(o1) * ai;
    g_out0[(size_t)wp * 64 + j] = o0;
    g_out0[(size_t)wp * 64 + 32 + j] = o1;
}

// ---- layer 1+2: agg(out0',64) -> @W1+b1 -> leaky -> @W2 -> *a_i -> m2' ----
__global__ void __launch_bounds__(256) k_l1(const float* __restrict__ W1,
                                            const float* __restrict__ b1,
                                            const float* __restrict__ W2, int n) {
    __shared__ float sW1[64 * 64];
    __shared__ float sW2[64 * 32];
    __shared__ float sB1[64];
    __shared__ float sBuf[8][64];
    int tid = threadIdx.x;
    {
        const float4* w14 = reinterpret_cast<const float4*>(W1);
        float4* s14 = reinterpret_cast<float4*>(sW1);
        for (int idx = tid; idx < 1024; idx += 256) s14[idx] = w14[idx];
        const float4* w24 = reinterpret_cast<const float4*>(W2);
        float4* s24 = reinterpret_cast<float4*>(sW2);
        for (int idx = tid; idx < 512; idx += 256) s24[idx] = w24[idx];
        if (tid < 64) sB1[tid] = b1[tid];
    }
    __syncthreads();

    const unsigned full = 0xffffffffu;
    int wp = (blockIdx.x * 256 + tid) >> 5;
    int lane = tid & 31;
    int wl = tid >> 5;
    if (wp >= n) return;
    int cnt = g_indeg[wp];
    if (cnt > SLOT) cnt = SLOT;
    const int2* cs = g_csr + (size_t)wp * SLOT;
    int2 pkA = make_int2(0, 0);
    if (lane < cnt) pkA = cs[lane];
    int hh = lane >> 4, l = lane & 15;
    const float4* S4 = reinterpret_cast<const float4*>(g_out0);
    float4 a0 = make_float4(0.f, 0.f, 0.f, 0.f);
    float4 a1 = make_float4(0.f, 0.f, 0.f, 0.f);
    int c1 = cnt < 32 ? cnt : 32;
    // dual accumulators; e<=28 so lane indices e+2+hh <= 31
#pragma unroll 2
    for (int e = 0; e < c1; e += 4) {
        int eA = e + hh;
        int sA = __shfl_sync(full, pkA.x, eA);
        float wA = __int_as_float(__shfl_sync(full, pkA.y, eA));
        float4 vA = S4[(size_t)sA * 16 + l];
        a0.x += wA * vA.x; a0.y += wA * vA.y; a0.z += wA * vA.z; a0.w += wA * vA.w;
        int eB = e + 2 + hh;
        int sB_ = __shfl_sync(full, pkA.x, eB);
        float wB = __int_as_float(__shfl_sync(full, pkA.y, eB));
        float4 vB = S4[(size_t)sB_ * 16 + l];
        a1.x += wB * vB.x; a1.y += wB * vB.y; a1.z += wB * vB.z; a1.w += wB * vB.w;
    }
    for (int e = 32; e < cnt; e += 2) {      // rare tail
        int ee = e + hh;
        bool ok = ee < cnt;
        int2 pk = ok ? cs[ee] : make_int2(0, 0);
        float wgt = __int_as_float(pk.y);
        float4 v = S4[(size_t)pk.x * 16 + l];
        a0.x += wgt * v.x; a0.y += wgt * v.y; a0.z += wgt * v.z; a0.w += wgt * v.w;
    }
    float4 acc = make_float4(a0.x + a1.x, a0.y + a1.y, a0.z + a1.z, a0.w + a1.w);
    acc.x += __shfl_xor_sync(full, acc.x, 16);
    acc.y += __shfl_xor_sync(full, acc.y, 16);
    acc.z += __shfl_xor_sync(full, acc.z, 16);
    acc.w += __shfl_xor_sync(full, acc.w, 16);

    float ai = rsqrtf(g_deg[wp]);
    if (lane < 16) {
        acc.x *= ai; acc.y *= ai; acc.z *= ai; acc.w *= ai;
        reinterpret_cast<float4*>(sBuf[wl])[l] = acc;
    }
    __syncwarp();

    int j = lane;
    float y0 = sB1[j], y1 = sB1[j + 32];
#pragma unroll
    for (int k = 0; k < 64; k++) {
        float xk = sBuf[wl][k];
        y0 += xk * sW1[k * 64 + j];
        y1 += xk * sW1[k * 64 + j + 32];
    }
    y0 = lrelu(y0);
    y1 = lrelu(y1);
    __syncwarp();
    sBuf[wl][j] = y0;
    sBuf[wl][j + 32] = y1;
    __syncwarp();

    float z = 0.0f;
#pragma unroll
    for (int k = 0; k < 64; k++) z += sBuf[wl][k] * sW2[k * 32 + j];
    z *= ai;
    g_m2[(size_t)wp * 32 + j] = z;
}

// ---------------- final: agg(m2',32) * a_i + b2 -> out; restore zeros ------
__global__ void __launch_bounds__(256) k_final(const float* __restrict__ b2,
                                               float* __restrict__ Out, int n) {
    const unsigned full = 0xffffffffu;
    int wp = (blockIdx.x * 256 + threadIdx.x) >> 5;
    int lane = threadIdx.x & 31;
    if (wp >= n) return;
    int cnt = g_indeg[wp];
    if (cnt > SLOT) cnt = SLOT;
    float ai = rsqrtf(g_deg[wp]);
    const int2* cs = g_csr + (size_t)wp * SLOT;
    int2 pkA = make_int2(0, 0);
    if (lane < cnt) pkA = cs[lane];
    // restore the zero-on-entry invariant for the next launch
    if (lane == 0) g_indeg[wp] = 0;
    if (lane == 1) g_deg[wp] = 0.0f;
    int q = lane >> 3, l = lane & 7;
    const float4* S4 = reinterpret_cast<const float4*>(g_m2);
    float4 a0 = make_float4(0.f, 0.f, 0.f, 0.f);
    float4 a1 = make_float4(0.f, 0.f, 0.f, 0.f);
    int c1 = cnt < 32 ? cnt : 32;
#pragma unroll 2
    for (int e = 0; e < c1; e += 8) {
        int eA = e + q;
        int sA = __shfl_sync(full, pkA.x, eA);
        float wA = __int_as_float(__shfl_sync(full, pkA.y, eA));
        float4 vA = S4[(size_t)sA * 8 + l];
        a0.x += wA * vA.x; a0.y += wA * vA.y; a0.z += wA * vA.z; a0.w += wA * vA.w;
        int eB = e + 4 + q;
        int sB_ = __shfl_sync(full, pkA.x, eB);
        float wB = __int_as_float(__shfl_sync(full, pkA.y, eB));
        float4 vB = S4[(size_t)sB_ * 8 + l];
        a1.x += wB * vB.x; a1.y += wB * vB.y; a1.z += wB * vB.z; a1.w += wB * vB.w;
    }
    for (int e = 32; e < cnt; e += 4) {      // rare tail
        int ee = e + q;
        bool ok = ee < cnt;
        int2 pk = ok ? cs[ee] : make_int2(0, 0);
        float wgt = __int_as_float(pk.y);
        float4 v = S4[(size_t)pk.x * 8 + l];
        a0.x += wgt * v.x; a0.y += wgt * v.y; a0.z += wgt * v.z; a0.w += wgt * v.w;
    }
    float4 acc = make_float4(a0.x + a1.x, a0.y + a1.y, a0.z + a1.z, a0.w + a1.w);
#pragma unroll
    for (int m = 8; m <= 16; m <<= 1) {
        acc.x += __shfl_xor_sync(full, acc.x, m);
        acc.y += __shfl_xor_sync(full, acc.y, m);
        acc.z += __shfl_xor_sync(full, acc.z, m);
        acc.w += __shfl_xor_sync(full, acc.w, m);
    }
    if (lane < 8) {
        float4 b = reinterpret_cast<const float4*>(b2)[lane];
        acc.x = acc.x * ai + b.x;
        acc.y = acc.y * ai + b.y;
        acc.z = acc.z * ai + b.z;
        acc.w = acc.w * ai + b.w;
        reinterpret_cast<float4*>(Out)[(size_t)wp * 8 + lane] = acc;
    }
}

// ---------------- launch ----------------
extern "C" void kernel_launch(void* const* d_in, const int* in_sizes, int n_in,
                              void* d_out, int out_size) {
    const float* feat = (const float*)d_in[0];
    const int* esrc = (const int*)d_in[1];
    const int* edst = (const int*)d_in[2];
    const float* ew = (const float*)d_in[3];
    const float* Wih = (const float*)d_in[4];
    const float* Whh = (const float*)d_in[5];
    const float* bih = (const float*)d_in[6];
    const float* bhh = (const float*)d_in[7];
    const float* W0 = (const float*)d_in[8];
    const float* b0 = (const float*)d_in[9];
    const float* W1 = (const float*)d_in[10];
    const float* b1 = (const float*)d_in[11];
    const float* W2 = (const float*)d_in[12];
    const float* b2 = (const float*)d_in[13];
    float* out = (float*)d_out;

    int n = in_sizes[0] / 8;
    int E = in_sizes[1];

    const int TB = 256;
    int aggBlocks = (n * 32 + TB - 1) / TB;
    int nbN = (n + 255) / 256;
    int edgeThreads = (E + 3) / 4;
    int nbE = (edgeThreads + TB - 1) / TB;

    // launches: pre(0), lstm(1), l0(2), l1(3 <- ncu capture), final(4)
    k_pre<<<nbN + nbE, TB>>>(feat, Wih, bih, bhh, esrc, edst, ew, n, E, nbN);
    k_lstm<<<(n + 127) / 128, 128>>>(Whh, bih, bhh, n);
    k_l0<<<aggBlocks, TB>>>(W0, b0, n);
    k_l1<<<aggBlocks, TB>>>(W1, b1, W2, n);
    k_final<<<aggBlocks, TB>>>(b2, out, n);
}

// round 15
// speedup vs baseline: 1.0302x; 1.0302x over previous
#include <cuda_runtime.h>

#define N_MAX 100000
#define SLOT 64

// ---------------- scratch (zero-initialized at module load; k_final
// restores g_deg/g_indeg to zero after use -> zero-on-entry invariant) ------
__device__ __align__(16) float g_featn[N_MAX * 8];
__device__ __align__(16) float g_U[N_MAX * 64];      // gate-interleaved [i][j(16)][gate(4)]
__device__ __align__(16) float g_h0[N_MAX * 32];     // a_i * [featn(8) | h(16) | 0(8)]
__device__ float g_deg[N_MAX];
__device__ int   g_indeg[N_MAX];
__device__ __align__(16) int2 g_csr[N_MAX * SLOT];   // packed (src, ew bits)
__device__ __align__(16) float g_out0[N_MAX * 64];   // a_i * leaky(...)
__device__ __align__(16) float g_agg[N_MAX * 64];    // x = a_i * agg(out0')
__device__ __align__(16) float g_m2[N_MAX * 32];     // a_i * (y @ W2)

// ---------------- activations ----------------
__device__ __forceinline__ float fsig(float x) {
    return __fdividef(1.0f, 1.0f + __expf(-x));
}
__device__ __forceinline__ float ftanh_(float x) {
    return 1.0f - __fdividef(2.0f, __expf(2.0f * x) + 1.0f);
}
__device__ __forceinline__ float lrelu(float v) { return v > 0.0f ? v : 0.01f * v; }

// ---------------- fused pre-pass: norm+U blocks || edge blocks -------------
__global__ void __launch_bounds__(256) k_pre(const float* __restrict__ feat,
                                             const float* __restrict__ Wih,
                                             const float* __restrict__ bih,
                                             const float* __restrict__ bhh,
                                             const int* __restrict__ esrc,
                                             const int* __restrict__ edst,
                                             const float* __restrict__ ew,
                                             int n, int E, int nbN) {
    int tid = threadIdx.x;
    if ((int)blockIdx.x < nbN) {
        __shared__ __align__(16) float sWI[512];  // [j(16)][k(8)][gate(4)]
        __shared__ __align__(16) float sB[64];
        for (int idx = tid; idx < 512; idx += 256) {
            int g = idx & 3, k = (idx >> 2) & 7, j = idx >> 5;
            sWI[idx] = Wih[(j + 16 * g) * 8 + k];
        }
        if (tid < 64) {
            int g = tid & 3, j = tid >> 2;
            sB[tid] = bih[j + 16 * g] + bhh[j + 16 * g];
        }
        __syncthreads();
        int i = blockIdx.x * 256 + tid;
        if (i >= n) return;

        const float4* f4 = reinterpret_cast<const float4*>(feat + (size_t)i * 8);
        float4 a = f4[0], b = f4[1];
        float v[8] = {a.x, a.y, a.z, a.w, b.x, b.y, b.z, b.w};
        float s = 0.0f;
#pragma unroll
        for (int k = 0; k < 8; k++) s += v[k];
        float inv = __fdividef(1.0f, s);
#pragma unroll
        for (int k = 0; k < 8; k++) v[k] *= inv;
        float4* o4 = reinterpret_cast<float4*>(g_featn + (size_t)i * 8);
        o4[0] = make_float4(v[0], v[1], v[2], v[3]);
        o4[1] = make_float4(v[4], v[5], v[6], v[7]);

        const float4* W4 = reinterpret_cast<const float4*>(sWI);
        const float4* B4 = reinterpret_cast<const float4*>(sB);
        float4* u4 = reinterpret_cast<float4*>(g_U + (size_t)i * 64);
#pragma unroll
        for (int j = 0; j < 16; j++) {
            float4 acc = B4[j];
#pragma unroll
            for (int k = 0; k < 8; k++) {
                float4 w = W4[j * 8 + k];
                acc.x += v[k] * w.x; acc.y += v[k] * w.y;
                acc.z += v[k] * w.z; acc.w += v[k] * w.w;
            }
            u4[j] = acc;
        }
    } else {
        int e0 = ((blockIdx.x - nbN) * 256 + tid) * 4;
        if (e0 >= E) return;
        if (e0 + 4 <= E) {
            int4 s4 = *reinterpret_cast<const int4*>(esrc + e0);
            int4 d4 = *reinterpret_cast<const int4*>(edst + e0);
            float4 w4 = *reinterpret_cast<const float4*>(ew + e0);

            int cur = s4.x;
            float acc = w4.x;
            if (s4.y == cur) acc += w4.y;
            else { atomicAdd(&g_deg[cur], acc); cur = s4.y; acc = w4.y; }
            if (s4.z == cur) acc += w4.z;
            else { atomicAdd(&g_deg[cur], acc); cur = s4.z; acc = w4.z; }
            if (s4.w == cur) acc += w4.w;
            else { atomicAdd(&g_deg[cur], acc); cur = s4.w; acc = w4.w; }
            atomicAdd(&g_deg[cur], acc);

            int p;
            p = atomicAdd(&g_indeg[d4.x], 1);
            if (p < SLOT) g_csr[(size_t)d4.x * SLOT + p] = make_int2(s4.x, __float_as_int(w4.x));
            p = atomicAdd(&g_indeg[d4.y], 1);
            if (p < SLOT) g_csr[(size_t)d4.y * SLOT + p] = make_int2(s4.y, __float_as_int(w4.y));
            p = atomicAdd(&g_indeg[d4.z], 1);
            if (p < SLOT) g_csr[(size_t)d4.z * SLOT + p] = make_int2(s4.z, __float_as_int(w4.z));
            p = atomicAdd(&g_indeg[d4.w], 1);
            if (p < SLOT) g_csr[(size_t)d4.w * SLOT + p] = make_int2(s4.w, __float_as_int(w4.w));
        } else {
            for (int e = e0; e < E; e++) {
                int s = esrc[e];
                float w = ew[e];
                atomicAdd(&g_deg[s], w);
                int d = edst[e];
                int p = atomicAdd(&g_indeg[d], 1);
                if (p < SLOT) g_csr[(size_t)d * SLOT + p] = make_int2(s, __float_as_int(w));
            }
        }
    }
}

// ---------------- LSTM: SMEM window staging + split gate chains -----------
#define UROWS 133
#define USTRIDE 68
__global__ void __launch_bounds__(128) k_lstm(const float* __restrict__ Whh,
                                              const float* __restrict__ bih,
                                              const float* __restrict__ bhh, int n) {
    __shared__ __align__(16) float sWhh[1024];
    __shared__ __align__(16) float sB[64];
    __shared__ __align__(16) float sU[UROWS * USTRIDE];
    int tid = threadIdx.x;
    for (int idx = tid; idx < 1024; idx += 128) {
        int g = idx & 3, k = (idx >> 2) & 15, j = idx >> 6;
        sWhh[idx] = Whh[(j + 16 * g) * 16 + k];
    }
    if (tid < 64) {
        int g = tid & 3, j = tid >> 2;
        sB[tid] = bih[j + 16 * g] + bhh[j + 16 * g];
    }

    int gbase = blockIdx.x * 128 - 5;
    const float4* U4 = reinterpret_cast<const float4*>(g_U);
    for (int idx = tid; idx < UROWS * 16; idx += 128) {
        int r = idx >> 4, c = idx & 15;
        int gr = gbase + r;
        float4 val = make_float4(0.f, 0.f, 0.f, 0.f);
        if (gr >= 0 && gr < n) val = U4[(size_t)gr * 16 + c];
        *reinterpret_cast<float4*>(sU + r * USTRIDE + c * 4) = val;
    }
    __syncthreads();

    int i = blockIdx.x * 128 + tid;
    if (i >= n) return;

    const float4* W4 = reinterpret_cast<const float4*>(sWhh);
    const float4* B4 = reinterpret_cast<const float4*>(sB);

    float h[16], c[16];
#pragma unroll
    for (int k = 0; k < 16; k++) { h[k] = 0.0f; c[k] = 0.0f; }

    int vmax = (i < 5) ? i : 5;
    int base = (i >= 5) ? (i - 5) : 0;

#pragma unroll 1
    for (int t = 0; t < 5; t++) {
        int gr = base + t;
        const float4* up = (t < vmax)
            ? reinterpret_cast<const float4*>(sU + (gr - gbase) * USTRIDE)
            : B4;
        float hn[16];
#pragma unroll 1
        for (int j = 0; j < 16; j++) {
            float4 u = up[j];
            float giA = u.x, gfA = u.y, ggA = u.z, goA = u.w;
            float giB = 0.f, gfB = 0.f, ggB = 0.f, goB = 0.f;
#pragma unroll
            for (int k = 0; k < 8; k++) {
                float4 w = W4[j * 16 + k];
                float hk = h[k];
                giA += hk * w.x; gfA += hk * w.y; ggA += hk * w.z; goA += hk * w.w;
            }
#pragma unroll
            for (int k = 8; k < 16; k++) {
                float4 w = W4[j * 16 + k];
                float hk = h[k];
                giB += hk * w.x; gfB += hk * w.y; ggB += hk * w.z; goB += hk * w.w;
            }
            float gi = giA + giB, gf = gfA + gfB, gg = ggA + ggB, go = goA + goB;
            float cj = fsig(gf) * c[j] + fsig(gi) * ftanh_(gg);
            c[j] = cj;
            hn[j] = fsig(go) * ftanh_(cj);
        }
#pragma unroll
        for (int j = 0; j < 16; j++) h[j] = hn[j];
    }

    float ai = rsqrtf(g_deg[i]);
    float4* o4 = reinterpret_cast<float4*>(g_h0 + (size_t)i * 32);
    const float4* f4 = reinterpret_cast<const float4*>(g_featn + (size_t)i * 8);
    float4 fa = f4[0], fb = f4[1];
    o4[0] = make_float4(fa.x * ai, fa.y * ai, fa.z * ai, fa.w * ai);
    o4[1] = make_float4(fb.x * ai, fb.y * ai, fb.z * ai, fb.w * ai);
    o4[2] = make_float4(h[0] * ai, h[1] * ai, h[2] * ai, h[3] * ai);
    o4[3] = make_float4(h[4] * ai, h[5] * ai, h[6] * ai, h[7] * ai);
    o4[4] = make_float4(h[8] * ai, h[9] * ai, h[10] * ai, h[11] * ai);
    o4[5] = make_float4(h[12] * ai, h[13] * ai, h[14] * ai, h[15] * ai);
    o4[6] = make_float4(0.f, 0.f, 0.f, 0.f);
    o4[7] = make_float4(0.f, 0.f, 0.f, 0.f);
}

// ---------------- layer 0: agg(h0', 24) -> @W0+b0 -> leaky -> *a_i ----------
__global__ void __launch_bounds__(256) k_l0(const float* __restrict__ W0,
                                            const float* __restrict__ b0, int n) {
    __shared__ float sW[24 * 64];
    __shared__ float sBv[64];
    int tid = threadIdx.x;
    for (int idx = tid; idx < 24 * 64; idx += 256) sW[idx] = W0[idx];
    if (tid < 64) sBv[tid] = b0[tid];
    __syncthreads();

    const unsigned full = 0xffffffffu;
    int wp = (blockIdx.x * 256 + tid) >> 5;
    int lane = tid & 31;
    if (wp >= n) return;
    int cnt = g_indeg[wp];
    if (cnt > SLOT) cnt = SLOT;
    const int2* cs = g_csr + (size_t)wp * SLOT;
    int2 pkA = make_int2(0, 0);
    if (lane < cnt) pkA = cs[lane];
    int q = lane >> 3, l = lane & 7;
    const float4* S4 = reinterpret_cast<const float4*>(g_h0);
    float4 a0 = make_float4(0.f, 0.f, 0.f, 0.f);
    float4 a1 = make_float4(0.f, 0.f, 0.f, 0.f);
    int c1 = cnt < 32 ? cnt : 32;
#pragma unroll 2
    for (int e = 0; e < c1; e += 8) {
        int eA = e + q;
        int sA = __shfl_sync(full, pkA.x, eA);
        float wA = __int_as_float(__shfl_sync(full, pkA.y, eA));
        float4 vA = S4[(size_t)sA * 8 + l];
        a0.x += wA * vA.x; a0.y += wA * vA.y; a0.z += wA * vA.z; a0.w += wA * vA.w;
        int eB = e + 4 + q;
        int sB_ = __shfl_sync(full, pkA.x, eB);
        float wB = __int_as_float(__shfl_sync(full, pkA.y, eB));
        float4 vB = S4[(size_t)sB_ * 8 + l];
        a1.x += wB * vB.x; a1.y += wB * vB.y; a1.z += wB * vB.z; a1.w += wB * vB.w;
    }
    for (int e = 32; e < cnt; e += 4) {
        int ee = e + q;
        bool ok = ee < cnt;
        int2 pk = ok ? cs[ee] : make_int2(0, 0);
        float wgt = __int_as_float(pk.y);
        float4 v = S4[(size_t)pk.x * 8 + l];
        a0.x += wgt * v.x; a0.y += wgt * v.y; a0.z += wgt * v.z; a0.w += wgt * v.w;
    }
    float4 acc = make_float4(a0.x + a1.x, a0.y + a1.y, a0.z + a1.z, a0.w + a1.w);
#pragma unroll
    for (int m = 8; m <= 16; m <<= 1) {
        acc.x += __shfl_xor_sync(full, acc.x, m);
        acc.y += __shfl_xor_sync(full, acc.y, m);
        acc.z += __shfl_xor_sync(full, acc.z, m);
        acc.w += __shfl_xor_sync(full, acc.w, m);
    }
    float ai = rsqrtf(g_deg[wp]);
    acc.x *= ai; acc.y *= ai; acc.z *= ai; acc.w *= ai;

    float t[24];
#pragma unroll
    for (int k = 0; k < 24; k++) {
        float src = ((k & 3) == 0) ? acc.x : ((k & 3) == 1) ? acc.y : ((k & 3) == 2) ? acc.z : acc.w;
        t[k] = __shfl_sync(full, src, k >> 2);
    }
    int j = lane;
    float o0 = sBv[j], o1 = sBv[j + 32];
#pragma unroll
    for (int k = 0; k < 24; k++) {
        o0 += t[k] * sW[k * 64 + j];
        o1 += t[k] * sW[k * 64 + j + 32];
    }
    o0 = lrelu(o0) * ai;
    o1 = lrelu(o1) * ai;
    g_out0[(size_t)wp * 64 + j] = o0;
    g_out0[(size_t)wp * 64 + 32 + j] = o1;
}

// ---------------- agg64: x = a_i * agg(out0') -> g_agg ----------------
__global__ void __launch_bounds__(256) k_agg64(int n) {
    const unsigned full = 0xffffffffu;
    int wp = (blockIdx.x * 256 + threadIdx.x) >> 5;
    int lane = threadIdx.x & 31;
    if (wp >= n) return;
    int cnt = g_indeg[wp];
    if (cnt > SLOT) cnt = SLOT;
    const int2* cs = g_csr + (size_t)wp * SLOT;
    int2 pkA = make_int2(0, 0);
    if (lane < cnt) pkA = cs[lane];
    int hh = lane >> 4, l = lane & 15;
    const float4* S4 = reinterpret_cast<const float4*>(g_out0);
    float4 a0 = make_float4(0.f, 0.f, 0.f, 0.f);
    float4 a1 = make_float4(0.f, 0.f, 0.f, 0.f);
    int c1 = cnt < 32 ? cnt : 32;
#pragma unroll 2
    for (int e = 0; e < c1; e += 4) {
        int eA = e + hh;
        int sA = __shfl_sync(full, pkA.x, eA);
        float wA = __int_as_float(__shfl_sync(full, pkA.y, eA));
        float4 vA = S4[(size_t)sA * 16 + l];
        a0.x += wA * vA.x; a0.y += wA * vA.y; a0.z += wA * vA.z; a0.w += wA * vA.w;
        int eB = e + 2 + hh;
        int sB_ = __shfl_sync(full, pkA.x, eB);
        float wB = __int_as_float(__shfl_sync(full, pkA.y, eB));
        float4 vB = S4[(size_t)sB_ * 16 + l];
        a1.x += wB * vB.x; a1.y += wB * vB.y; a1.z += wB * vB.z; a1.w += wB * vB.w;
    }
    for (int e = 32; e < cnt; e += 2) {
        int ee = e + hh;
        bool ok = ee < cnt;
        int2 pk = ok ? cs[ee] : make_int2(0, 0);
        float wgt = __int_as_float(pk.y);
        float4 v = S4[(size_t)pk.x * 16 + l];
        a0.x += wgt * v.x; a0.y += wgt * v.y; a0.z += wgt * v.z; a0.w += wgt * v.w;
    }
    float4 acc = make_float4(a0.x + a1.x, a0.y + a1.y, a0.z + a1.z, a0.w + a1.w);
    acc.x += __shfl_xor_sync(full, acc.x, 16);
    acc.y += __shfl_xor_sync(full, acc.y, 16);
    acc.z += __shfl_xor_sync(full, acc.z, 16);
    acc.w += __shfl_xor_sync(full, acc.w, 16);
    if (lane < 16) {
        float ai = rsqrtf(g_deg[wp]);
        acc.x *= ai; acc.y *= ai; acc.z *= ai; acc.w *= ai;
        reinterpret_cast<float4*>(g_agg)[(size_t)wp * 16 + lane] = acc;
    }
}

// ---- gemm12: thread-per-node, z = a_i*(leaky(x@W1+b1) @ W2) -> g_m2 -------
// weight reads are warp-broadcast SMEM loads: 24KB per 32 nodes (32x less
// crossbar traffic than the warp-per-node epilogue).
__global__ void __launch_bounds__(256) k_gemm12(const float* __restrict__ W1,
                                                const float* __restrict__ b1,
                                                const float* __restrict__ W2, int n) {
    __shared__ float4 sW1[1024];  // [k(64)][j4(16)]
    __shared__ float4 sW2[512];   // [k(64)][j4(8)]
    __shared__ float sB1[64];
    int tid = threadIdx.x;
    {
        const float4* w14 = reinterpret_cast<const float4*>(W1);
        for (int idx = tid; idx < 1024; idx += 256) sW1[idx] = w14[idx];
        const float4* w24 = reinterpret_cast<const float4*>(W2);
        for (int idx = tid; idx < 512; idx += 256) sW2[idx] = w24[idx];
        if (tid < 64) sB1[tid] = b1[tid];
    }
    __syncthreads();
    int i = blockIdx.x * 256 + tid;
    if (i >= n) return;

    const float4* x4 = reinterpret_cast<const float4*>(g_agg + (size_t)i * 64);
    float y[64];
#pragma unroll
    for (int j = 0; j < 64; j++) y[j] = sB1[j];

    // phase 1: y += x @ W1  (unroll 1 on k4 to keep live set small)
#pragma unroll 1
    for (int k4 = 0; k4 < 16; k4++) {
        float4 xv = x4[k4];
        float xk[4] = {xv.x, xv.y, xv.z, xv.w};
#pragma unroll
        for (int kk = 0; kk < 4; kk++) {
            int k = k4 * 4 + kk;
#pragma unroll
            for (int j4 = 0; j4 < 16; j4++) {
                float4 w = sW1[k * 16 + j4];
                y[j4 * 4] += xk[kk] * w.x;
                y[j4 * 4 + 1] += xk[kk] * w.y;
                y[j4 * 4 + 2] += xk[kk] * w.z;
                y[j4 * 4 + 3] += xk[kk] * w.w;
            }
        }
    }
#pragma unroll
    for (int j = 0; j < 64; j++) y[j] = lrelu(y[j]);

    // phase 2: z = y @ W2
    float z[32];
#pragma unroll
    for (int j = 0; j < 32; j++) z[j] = 0.0f;
#pragma unroll 2
    for (int k = 0; k < 64; k++) {
        float yk = y[k];
#pragma unroll
        for (int j4 = 0; j4 < 8; j4++) {
            float4 w = sW2[k * 8 + j4];
            z[j4 * 4] += yk * w.x;
            z[j4 * 4 + 1] += yk * w.y;
            z[j4 * 4 + 2] += yk * w.z;
            z[j4 * 4 + 3] += yk * w.w;
        }
    }
    float ai = rsqrtf(g_deg[i]);
    float4* o4 = reinterpret_cast<float4*>(g_m2 + (size_t)i * 32);
#pragma unroll
    for (int j4 = 0; j4 < 8; j4++) {
        o4[j4] = make_float4(z[j4 * 4] * ai, z[j4 * 4 + 1] * ai,
                             z[j4 * 4 + 2] * ai, z[j4 * 4 + 3] * ai);
    }
}

// ---------------- final: agg(m2',32) * a_i + b2 -> out; restore zeros ------
__global__ void __launch_bounds__(256) k_final(const float* __restrict__ b2,
                                               float* __restrict__ Out, int n) {
    const unsigned full = 0xffffffffu;
    int wp = (blockIdx.x * 256 + threadIdx.x) >> 5;
    int lane = threadIdx.x & 31;
    if (wp >= n) return;
    int cnt = g_indeg[wp];
    if (cnt > SLOT) cnt = SLOT;
    float ai = rsqrtf(g_deg[wp]);
    const int2* cs = g_csr + (size_t)wp * SLOT;
    int2 pkA = make_int2(0, 0);
    if (lane < cnt) pkA = cs[lane];
    if (lane == 0) g_indeg[wp] = 0;
    if (lane == 1) g_deg[wp] = 0.0f;
    int q = lane >> 3, l = lane & 7;
    const float4* S4 = reinterpret_cast<const float4*>(g_m2);
    float4 a0 = make_float4(0.f, 0.f, 0.f, 0.f);
    float4 a1 = make_float4(0.f, 0.f, 0.f, 0.f);
    int c1 = cnt < 32 ? cnt : 32;
#pragma unroll 2
    for (int e = 0; e < c1; e += 8) {
        int eA = e + q;
        int sA = __shfl_sync(full, pkA.x, eA);
        float wA = __int_as_float(__shfl_sync(full, pkA.y, eA));
        float4 vA = S4[(size_t)sA * 8 + l];
        a0.x += wA * vA.x; a0.y += wA * vA.y; a0.z += wA * vA.z; a0.w += wA * vA.w;
        int eB = e + 4 + q;
        int sB_ = __shfl_sync(full, pkA.x, eB);
        float wB = __int_as_float(__shfl_sync(full, pkA.y, eB));
        float4 vB = S4[(size_t)sB_ * 8 + l];
        a1.x += wB * vB.x; a1.y += wB * vB.y; a1.z += wB * vB.z; a1.w += wB * vB.w;
    }
    for (int e = 32; e < cnt; e += 4) {
        int ee = e + q;
        bool ok = ee < cnt;
        int2 pk = ok ? cs[ee] : make_int2(0, 0);
        float wgt = __int_as_float(pk.y);
        float4 v = S4[(size_t)pk.x * 8 + l];
        a0.x += wgt * v.x; a0.y += wgt * v.y; a0.z += wgt * v.z; a0.w += wgt * v.w;
    }
    float4 acc = make_float4(a0.x + a1.x, a0.y + a1.y, a0.z + a1.z, a0.w + a1.w);
#pragma unroll
    for (int m = 8; m <= 16; m <<= 1) {
        acc.x += __shfl_xor_sync(full, acc.x, m);
        acc.y += __shfl_xor_sync(full, acc.y, m);
        acc.z += __shfl_xor_sync(full, acc.z, m);
        acc.w += __shfl_xor_sync(full, acc.w, m);
    }
    if (lane < 8) {
        float4 b = reinterpret_cast<const float4*>(b2)[lane];
        acc.x = acc.x * ai + b.x;
        acc.y = acc.y * ai + b.y;
        acc.z = acc.z * ai + b.z;
        acc.w = acc.w * ai + b.w;
        reinterpret_cast<float4*>(Out)[(size_t)wp * 8 + lane] = acc;
    }
}

// ---------------- launch ----------------
extern "C" void kernel_launch(void* const* d_in, const int* in_sizes, int n_in,
                              void* d_out, int out_size) {
    const float* feat = (const float*)d_in[0];
    const int* esrc = (const int*)d_in[1];
    const int* edst = (const int*)d_in[2];
    const float* ew = (const float*)d_in[3];
    const float* Wih = (const float*)d_in[4];
    const float* Whh = (const float*)d_in[5];
    const float* bih = (const float*)d_in[6];
    const float* bhh = (const float*)d_in[7];
    const float* W0 = (const float*)d_in[8];
    const float* b0 = (const float*)d_in[9];
    const float* W1 = (const float*)d_in[10];
    const float* b1 = (const float*)d_in[11];
    const float* W2 = (const float*)d_in[12];
    const float* b2 = (const float*)d_in[13];
    float* out = (float*)d_out;

    int n = in_sizes[0] / 8;
    int E = in_sizes[1];

    const int TB = 256;
    int aggBlocks = (n * 32 + TB - 1) / TB;
    int nbN = (n + 255) / 256;
    int edgeThreads = (E + 3) / 4;
    int nbE = (edgeThreads + TB - 1) / TB;

    // launches: pre(0), lstm(1), l0(2), agg64(3 <- ncu capture), gemm12(4), final(5)
    k_pre<<<nbN + nbE, TB>>>(feat, Wih, bih, bhh, esrc, edst, ew, n, E, nbN);
    k_lstm<<<(n + 127) / 128, 128>>>(Whh, bih, bhh, n);
    k_l0<<<aggBlocks, TB>>>(W0, b0, n);
    k_agg64<<<aggBlocks, TB>>>(n);
    k_gemm12<<<(n + 255) / 256, TB>>>(W1, b1, W2, n);
    k_final<<<aggBlocks, TB>>>(b2, out, n);
}

// round 16
// speedup vs baseline: 1.0365x; 1.0061x over previous
#include <cuda_runtime.h>

#define N_MAX 100000
#define SLOT 64

// ---------------- scratch (zero-initialized at module load; k_final
// restores g_deg/g_indeg to zero after use -> zero-on-entry invariant) ------
__device__ __align__(16) float g_featn[N_MAX * 8];
__device__ __align__(16) float g_U[N_MAX * 64];      // gate-interleaved [i][j(16)][gate(4)]
__device__ __align__(16) float g_h0[N_MAX * 32];     // a_i * [featn(8) | h(16) | 0(8)]
__device__ float g_deg[N_MAX];
__device__ int   g_indeg[N_MAX];
__device__ __align__(16) int2 g_csr[N_MAX * SLOT];   // packed (src, ew bits)
__device__ __align__(16) float g_x24[N_MAX * 32];    // a_i * agg(h0')  (24 live cols)
__device__ __align__(16) float g_out0[N_MAX * 64];   // a_i * leaky(...)
__device__ __align__(16) float g_agg[N_MAX * 64];    // x = a_i * agg(out0')
__device__ __align__(16) float g_m2[N_MAX * 32];     // a_i * (y @ W2)

// ---------------- activations ----------------
__device__ __forceinline__ float fsig(float x) {
    return __fdividef(1.0f, 1.0f + __expf(-x));
}
__device__ __forceinline__ float ftanh_(float x) {
    return 1.0f - __fdividef(2.0f, __expf(2.0f * x) + 1.0f);
}
__device__ __forceinline__ float lrelu(float v) { return v > 0.0f ? v : 0.01f * v; }

// ---------------- fused pre-pass: norm+U blocks || edge blocks -------------
__global__ void __launch_bounds__(256) k_pre(const float* __restrict__ feat,
                                             const float* __restrict__ Wih,
                                             const float* __restrict__ bih,
                                             const float* __restrict__ bhh,
                                             const int* __restrict__ esrc,
                                             const int* __restrict__ edst,
                                             const float* __restrict__ ew,
                                             int n, int E, int nbN) {
    int tid = threadIdx.x;
    if ((int)blockIdx.x < nbN) {
        __shared__ __align__(16) float sWI[512];  // [j(16)][k(8)][gate(4)]
        __shared__ __align__(16) float sB[64];
        for (int idx = tid; idx < 512; idx += 256) {
            int g = idx & 3, k = (idx >> 2) & 7, j = idx >> 5;
            sWI[idx] = Wih[(j + 16 * g) * 8 + k];
        }
        if (tid < 64) {
            int g = tid & 3, j = tid >> 2;
            sB[tid] = bih[j + 16 * g] + bhh[j + 16 * g];
        }
        __syncthreads();
        int i = blockIdx.x * 256 + tid;
        if (i >= n) return;

        const float4* f4 = reinterpret_cast<const float4*>(feat + (size_t)i * 8);
        float4 a = f4[0], b = f4[1];
        float v[8] = {a.x, a.y, a.z, a.w, b.x, b.y, b.z, b.w};
        float s = 0.0f;
#pragma unroll
        for (int k = 0; k < 8; k++) s += v[k];
        float inv = __fdividef(1.0f, s);
#pragma unroll
        for (int k = 0; k < 8; k++) v[k] *= inv;
        float4* o4 = reinterpret_cast<float4*>(g_featn + (size_t)i * 8);
        o4[0] = make_float4(v[0], v[1], v[2], v[3]);
        o4[1] = make_float4(v[4], v[5], v[6], v[7]);

        const float4* W4 = reinterpret_cast<const float4*>(sWI);
        const float4* B4 = reinterpret_cast<const float4*>(sB);
        float4* u4 = reinterpret_cast<float4*>(g_U + (size_t)i * 64);
#pragma unroll
        for (int j = 0; j < 16; j++) {
            float4 acc = B4[j];
#pragma unroll
            for (int k = 0; k < 8; k++) {
                float4 w = W4[j * 8 + k];
                acc.x += v[k] * w.x; acc.y += v[k] * w.y;
                acc.z += v[k] * w.z; acc.w += v[k] * w.w;
            }
            u4[j] = acc;
        }
    } else {
        int e0 = ((blockIdx.x - nbN) * 256 + tid) * 4;
        if (e0 >= E) return;
        if (e0 + 4 <= E) {
            int4 s4 = *reinterpret_cast<const int4*>(esrc + e0);
            int4 d4 = *reinterpret_cast<const int4*>(edst + e0);
            float4 w4 = *reinterpret_cast<const float4*>(ew + e0);

            int cur = s4.x;
            float acc = w4.x;
            if (s4.y == cur) acc += w4.y;
            else { atomicAdd(&g_deg[cur], acc); cur = s4.y; acc = w4.y; }
            if (s4.z == cur) acc += w4.z;
            else { atomicAdd(&g_deg[cur], acc); cur = s4.z; acc = w4.z; }
            if (s4.w == cur) acc += w4.w;
            else { atomicAdd(&g_deg[cur], acc); cur = s4.w; acc = w4.w; }
            atomicAdd(&g_deg[cur], acc);

            int p;
            p = atomicAdd(&g_indeg[d4.x], 1);
            if (p < SLOT) g_csr[(size_t)d4.x * SLOT + p] = make_int2(s4.x, __float_as_int(w4.x));
            p = atomicAdd(&g_indeg[d4.y], 1);
            if (p < SLOT) g_csr[(size_t)d4.y * SLOT + p] = make_int2(s4.y, __float_as_int(w4.y));
            p = atomicAdd(&g_indeg[d4.z], 1);
            if (p < SLOT) g_csr[(size_t)d4.z * SLOT + p] = make_int2(s4.z, __float_as_int(w4.z));
            p = atomicAdd(&g_indeg[d4.w], 1);
            if (p < SLOT) g_csr[(size_t)d4.w * SLOT + p] = make_int2(s4.w, __float_as_int(w4.w));
        } else {
            for (int e = e0; e < E; e++) {
                int s = esrc[e];
                float w = ew[e];
                atomicAdd(&g_deg[s], w);
                int d = edst[e];
                int p = atomicAdd(&g_indeg[d], 1);
                if (p < SLOT) g_csr[(size_t)d * SLOT + p] = make_int2(s, __float_as_int(w));
            }
        }
    }
}

// ---------------- LSTM: SMEM window staging + split gate chains -----------
#define UROWS 133
#define USTRIDE 68
__global__ void __launch_bounds__(128) k_lstm(const float* __restrict__ Whh,
                                              const float* __restrict__ bih,
                                              const float* __restrict__ bhh, int n) {
    __shared__ __align__(16) float sWhh[1024];
    __shared__ __align__(16) float sB[64];
    __shared__ __align__(16) float sU[UROWS * USTRIDE];
    int tid = threadIdx.x;
    for (int idx = tid; idx < 1024; idx += 128) {
        int g = idx & 3, k = (idx >> 2) & 15, j = idx >> 6;
        sWhh[idx] = Whh[(j + 16 * g) * 16 + k];
    }
    if (tid < 64) {
        int g = tid & 3, j = tid >> 2;
        sB[tid] = bih[j + 16 * g] + bhh[j + 16 * g];
    }

    int gbase = blockIdx.x * 128 - 5;
    const float4* U4 = reinterpret_cast<const float4*>(g_U);
    for (int idx = tid; idx < UROWS * 16; idx += 128) {
        int r = idx >> 4, c = idx & 15;
        int gr = gbase + r;
        float4 val = make_float4(0.f, 0.f, 0.f, 0.f);
        if (gr >= 0 && gr < n) val = U4[(size_t)gr * 16 + c];
        *reinterpret_cast<float4*>(sU + r * USTRIDE + c * 4) = val;
    }
    __syncthreads();

    int i = blockIdx.x * 128 + tid;
    if (i >= n) return;

    const float4* W4 = reinterpret_cast<const float4*>(sWhh);
    const float4* B4 = reinterpret_cast<const float4*>(sB);

    float h[16], c[16];
#pragma unroll
    for (int k = 0; k < 16; k++) { h[k] = 0.0f; c[k] = 0.0f; }

    int vmax = (i < 5) ? i : 5;
    int base = (i >= 5) ? (i - 5) : 0;

#pragma unroll 1
    for (int t = 0; t < 5; t++) {
        int gr = base + t;
        const float4* up = (t < vmax)
            ? reinterpret_cast<const float4*>(sU + (gr - gbase) * USTRIDE)
            : B4;
        float hn[16];
#pragma unroll 1
        for (int j = 0; j < 16; j++) {
            float4 u = up[j];
            float giA = u.x, gfA = u.y, ggA = u.z, goA = u.w;
            float giB = 0.f, gfB = 0.f, ggB = 0.f, goB = 0.f;
#pragma unroll
            for (int k = 0; k < 8; k++) {
                float4 w = W4[j * 16 + k];
                float hk = h[k];
                giA += hk * w.x; gfA += hk * w.y; ggA += hk * w.z; goA += hk * w.w;
            }
#pragma unroll
            for (int k = 8; k < 16; k++) {
                float4 w = W4[j * 16 + k];
                float hk = h[k];
                giB += hk * w.x; gfB += hk * w.y; ggB += hk * w.z; goB += hk * w.w;
            }
            float gi = giA + giB, gf = gfA + gfB, gg = ggA + ggB, go = goA + goB;
            float cj = fsig(gf) * c[j] + fsig(gi) * ftanh_(gg);
            c[j] = cj;
            hn[j] = fsig(go) * ftanh_(cj);
        }
#pragma unroll
        for (int j = 0; j < 16; j++) h[j] = hn[j];
    }

    float ai = rsqrtf(g_deg[i]);
    float4* o4 = reinterpret_cast<float4*>(g_h0 + (size_t)i * 32);
    const float4* f4 = reinterpret_cast<const float4*>(g_featn + (size_t)i * 8);
    float4 fa = f4[0], fb = f4[1];
    o4[0] = make_float4(fa.x * ai, fa.y * ai, fa.z * ai, fa.w * ai);
    o4[1] = make_float4(fb.x * ai, fb.y * ai, fb.z * ai, fb.w * ai);
    o4[2] = make_float4(h[0] * ai, h[1] * ai, h[2] * ai, h[3] * ai);
    o4[3] = make_float4(h[4] * ai, h[5] * ai, h[6] * ai, h[7] * ai);
    o4[4] = make_float4(h[8] * ai, h[9] * ai, h[10] * ai, h[11] * ai);
    o4[5] = make_float4(h[12] * ai, h[13] * ai, h[14] * ai, h[15] * ai);
    o4[6] = make_float4(0.f, 0.f, 0.f, 0.f);
    o4[7] = make_float4(0.f, 0.f, 0.f, 0.f);
}

// ---------------- agg24: x24 = a_i * agg(h0') -> g_x24 ----------------
__global__ void __launch_bounds__(256) k_agg24(int n) {
    const unsigned full = 0xffffffffu;
    int wp = (blockIdx.x * 256 + threadIdx.x) >> 5;
    int lane = threadIdx.x & 31;
    if (wp >= n) return;
    int cnt = g_indeg[wp];
    if (cnt > SLOT) cnt = SLOT;
    const int2* cs = g_csr + (size_t)wp * SLOT;
    int2 pkA = make_int2(0, 0);
    if (lane < cnt) pkA = cs[lane];
    int q = lane >> 3, l = lane & 7;
    const float4* S4 = reinterpret_cast<const float4*>(g_h0);
    float4 a0 = make_float4(0.f, 0.f, 0.f, 0.f);
    float4 a1 = make_float4(0.f, 0.f, 0.f, 0.f);
    int c1 = cnt < 32 ? cnt : 32;
#pragma unroll 2
    for (int e = 0; e < c1; e += 8) {
        int eA = e + q;
        int sA = __shfl_sync(full, pkA.x, eA);
        float wA = __int_as_float(__shfl_sync(full, pkA.y, eA));
        float4 vA = S4[(size_t)sA * 8 + l];
        a0.x += wA * vA.x; a0.y += wA * vA.y; a0.z += wA * vA.z; a0.w += wA * vA.w;
        int eB = e + 4 + q;
        int sB_ = __shfl_sync(full, pkA.x, eB);
        float wB = __int_as_float(__shfl_sync(full, pkA.y, eB));
        float4 vB = S4[(size_t)sB_ * 8 + l];
        a1.x += wB * vB.x; a1.y += wB * vB.y; a1.z += wB * vB.z; a1.w += wB * vB.w;
    }
    for (int e = 32; e < cnt; e += 4) {
        int ee = e + q;
        bool ok = ee < cnt;
        int2 pk = ok ? cs[ee] : make_int2(0, 0);
        float wgt = __int_as_float(pk.y);
        float4 v = S4[(size_t)pk.x * 8 + l];
        a0.x += wgt * v.x; a0.y += wgt * v.y; a0.z += wgt * v.z; a0.w += wgt * v.w;
    }
    float4 acc = make_float4(a0.x + a1.x, a0.y + a1.y, a0.z + a1.z, a0.w + a1.w);
#pragma unroll
    for (int m = 8; m <= 16; m <<= 1) {
        acc.x += __shfl_xor_sync(full, acc.x, m);
        acc.y += __shfl_xor_sync(full, acc.y, m);
        acc.z += __shfl_xor_sync(full, acc.z, m);
        acc.w += __shfl_xor_sync(full, acc.w, m);
    }
    if (lane < 8) {
        float ai = rsqrtf(g_deg[wp]);
        acc.x *= ai; acc.y *= ai; acc.z *= ai; acc.w *= ai;
        reinterpret_cast<float4*>(g_x24)[(size_t)wp * 8 + lane] = acc;
    }
}

// ---- gemm0: thread-per-node, out0' = a_i*leaky(x24@W0+b0) -----------------
__global__ void __launch_bounds__(256) k_gemm0(const float* __restrict__ W0,
                                               const float* __restrict__ b0, int n) {
    __shared__ float4 sW0[24 * 16];  // [k(24)][j4(16)]
    __shared__ float sB[64];
    int tid = threadIdx.x;
    {
        const float4* w04 = reinterpret_cast<const float4*>(W0);
        for (int idx = tid; idx < 24 * 16; idx += 256) sW0[idx] = w04[idx];
        if (tid < 64) sB[tid] = b0[tid];
    }
    __syncthreads();
    int i = blockIdx.x * 256 + tid;
    if (i >= n) return;

    const float4* x4 = reinterpret_cast<const float4*>(g_x24 + (size_t)i * 32);
    float y[64];
#pragma unroll
    for (int j = 0; j < 64; j++) y[j] = sB[j];

    float4 xv = x4[0];
#pragma unroll 1
    for (int k4 = 0; k4 < 6; k4++) {
        float4 nxt = (k4 < 5) ? x4[k4 + 1] : xv;   // prefetch next row chunk
        float xk[4] = {xv.x, xv.y, xv.z, xv.w};
#pragma unroll
        for (int kk = 0; kk < 4; kk++) {
            int k = k4 * 4 + kk;
#pragma unroll
            for (int j4 = 0; j4 < 16; j4++) {
                float4 w = sW0[k * 16 + j4];
                y[j4 * 4] += xk[kk] * w.x;
                y[j4 * 4 + 1] += xk[kk] * w.y;
                y[j4 * 4 + 2] += xk[kk] * w.z;
                y[j4 * 4 + 3] += xk[kk] * w.w;
            }
        }
        xv = nxt;
    }
    float ai = rsqrtf(g_deg[i]);
    float4* o4 = reinterpret_cast<float4*>(g_out0 + (size_t)i * 64);
#pragma unroll
    for (int j4 = 0; j4 < 16; j4++) {
        o4[j4] = make_float4(lrelu(y[j4 * 4]) * ai, lrelu(y[j4 * 4 + 1]) * ai,
                             lrelu(y[j4 * 4 + 2]) * ai, lrelu(y[j4 * 4 + 3]) * ai);
    }
}

// ---------------- agg64: x = a_i * agg(out0') -> g_agg ----------------
__global__ void __launch_bounds__(256) k_agg64(int n) {
    const unsigned full = 0xffffffffu;
    int wp = (blockIdx.x * 256 + threadIdx.x) >> 5;
    int lane = threadIdx.x & 31;
    if (wp >= n) return;
    int cnt = g_indeg[wp];
    if (cnt > SLOT) cnt = SLOT;
    const int2* cs = g_csr + (size_t)wp * SLOT;
    int2 pkA = make_int2(0, 0);
    if (lane < cnt) pkA = cs[lane];
    int hh = lane >> 4, l = lane & 15;
    const float4* S4 = reinterpret_cast<const float4*>(g_out0);
    float4 a0 = make_float4(0.f, 0.f, 0.f, 0.f);
    float4 a1 = make_float4(0.f, 0.f, 0.f, 0.f);
    int c1 = cnt < 32 ? cnt : 32;
#pragma unroll 2
    for (int e = 0; e < c1; e += 4) {
        int eA = e + hh;
        int sA = __shfl_sync(full, pkA.x, eA);
        float wA = __int_as_float(__shfl_sync(full, pkA.y, eA));
        float4 vA = S4[(size_t)sA * 16 + l];
        a0.x += wA * vA.x; a0.y += wA * vA.y; a0.z += wA * vA.z; a0.w += wA * vA.w;
        int eB = e + 2 + hh;
        int sB_ = __shfl_sync(full, pkA.x, eB);
        float wB = __int_as_float(__shfl_sync(full, pkA.y, eB));
        float4 vB = S4[(size_t)sB_ * 16 + l];
        a1.x += wB * vB.x; a1.y += wB * vB.y; a1.z += wB * vB.z; a1.w += wB * vB.w;
    }
    for (int e = 32; e < cnt; e += 2) {
        int ee = e + hh;
        bool ok = ee < cnt;
        int2 pk = ok ? cs[ee] : make_int2(0, 0);
        float wgt = __int_as_float(pk.y);
        float4 v = S4[(size_t)pk.x * 16 + l];
        a0.x += wgt * v.x; a0.y += wgt * v.y; a0.z += wgt * v.z; a0.w += wgt * v.w;
    }
    float4 acc = make_float4(a0.x + a1.x, a0.y + a1.y, a0.z + a1.z, a0.w + a1.w);
    acc.x += __shfl_xor_sync(full, acc.x, 16);
    acc.y += __shfl_xor_sync(full, acc.y, 16);
    acc.z += __shfl_xor_sync(full, acc.z, 16);
    acc.w += __shfl_xor_sync(full, acc.w, 16);
    if (lane < 16) {
        float ai = rsqrtf(g_deg[wp]);
        acc.x *= ai; acc.y *= ai; acc.z *= ai; acc.w *= ai;
        reinterpret_cast<float4*>(g_agg)[(size_t)wp * 16 + lane] = acc;
    }
}

// ---- gemm12: thread-per-node, z = a_i*(leaky(x@W1+b1) @ W2) -> g_m2 -------
__global__ void __launch_bounds__(256) k_gemm12(const float* __restrict__ W1,
                                                const float* __restrict__ b1,
                                                const float* __restrict__ W2, int n) {
    __shared__ float4 sW1[1024];  // [k(64)][j4(16)]
    __shared__ float4 sW2[512];   // [k(64)][j4(8)]
    __shared__ float sB1[64];
    int tid = threadIdx.x;
    {
        const float4* w14 = reinterpret_cast<const float4*>(W1);
        for (int idx = tid; idx < 1024; idx += 256) sW1[idx] = w14[idx];
        const float4* w24 = reinterpret_cast<const float4*>(W2);
        for (int idx = tid; idx < 512; idx += 256) sW2[idx] = w24[idx];
        if (tid < 64) sB1[tid] = b1[tid];
    }
    __syncthreads();
    int i = blockIdx.x * 256 + tid;
    if (i >= n) return;

    const float4* x4 = reinterpret_cast<const float4*>(g_agg + (size_t)i * 64);
    float y[64];
#pragma unroll
    for (int j = 0; j < 64; j++) y[j] = sB1[j];

    // phase 1: y += x @ W1; software-pipelined x loads (latency hidden under FMAs)
    float4 xv = x4[0];
#pragma unroll 1
    for (int k4 = 0; k4 < 16; k4++) {
        float4 nxt = (k4 < 15) ? x4[k4 + 1] : xv;
        float xk[4] = {xv.x, xv.y, xv.z, xv.w};
#pragma unroll
        for (int kk = 0; kk < 4; kk++) {
            int k = k4 * 4 + kk;
#pragma unroll
            for (int j4 = 0; j4 < 16; j4++) {
                float4 w = sW1[k * 16 + j4];
                y[j4 * 4] += xk[kk] * w.x;
                y[j4 * 4 + 1] += xk[kk] * w.y;
                y[j4 * 4 + 2] += xk[kk] * w.z;
                y[j4 * 4 + 3] += xk[kk] * w.w;
            }
        }
        xv = nxt;
    }
#pragma unroll
    for (int j = 0; j < 64; j++) y[j] = lrelu(y[j]);

    // phase 2: z = y @ W2
    float z[32];
#pragma unroll
    for (int j = 0; j < 32; j++) z[j] = 0.0f;
#pragma unroll 2
    for (int k = 0; k < 64; k++) {
        float yk = y[k];
#pragma unroll
        for (int j4 = 0; j4 < 8; j4++) {
            float4 w = sW2[k * 8 + j4];
            z[j4 * 4] += yk * w.x;
            z[j4 * 4 + 1] += yk * w.y;
            z[j4 * 4 + 2] += yk * w.z;
            z[j4 * 4 + 3] += yk * w.w;
        }
    }
    float ai = rsqrtf(g_deg[i]);
    float4* o4 = reinterpret_cast<float4*>(g_m2 + (size_t)i * 32);
#pragma unroll
    for (int j4 = 0; j4 < 8; j4++) {
        o4[j4] = make_float4(z[j4 * 4] * ai, z[j4 * 4 + 1] * ai,
                             z[j4 * 4 + 2] * ai, z[j4 * 4 + 3] * ai);
    }
}

// ---------------- final: agg(m2',32) * a_i + b2 -> out; restore zeros ------
__global__ void __launch_bounds__(256) k_final(const float* __restrict__ b2,
                                               float* __restrict__ Out, int n) {
    const unsigned full = 0xffffffffu;
    int wp = (blockIdx.x * 256 + threadIdx.x) >> 5;
    int lane = threadIdx.x & 31;
    if (wp >= n) return;
    int cnt = g_indeg[wp];
    if (cnt > SLOT) cnt = SLOT;
    float ai = rsqrtf(g_deg[wp]);
    const int2* cs = g_csr + (size_t)wp * SLOT;
    int2 pkA = make_int2(0, 0);
    if (lane < cnt) pkA = cs[lane];
    if (lane == 0) g_indeg[wp] = 0;
    if (lane == 1) g_deg[wp] = 0.0f;
    int q = lane >> 3, l = lane & 7;
    const float4* S4 = reinterpret_cast<const float4*>(g_m2);
    float4 a0 = make_float4(0.f, 0.f, 0.f, 0.f);
    float4 a1 = make_float4(0.f, 0.f, 0.f, 0.f);
    int c1 = cnt < 32 ? cnt : 32;
#pragma unroll 2
    for (int e = 0; e < c1; e += 8) {
        int eA = e + q;
        int sA = __shfl_sync(full, pkA.x, eA);
        float wA = __int_as_float(__shfl_sync(full, pkA.y, eA));
        float4 vA = S4[(size_t)sA * 8 + l];
        a0.x += wA * vA.x; a0.y += wA * vA.y; a0.z += wA * vA.z; a0.w += wA * vA.w;
        int eB = e + 4 + q;
        int sB_ = __shfl_sync(full, pkA.x, eB);
        float wB = __int_as_float(__shfl_sync(full, pkA.y, eB));
        float4 vB = S4[(size_t)sB_ * 8 + l];
        a1.x += wB * vB.x; a1.y += wB * vB.y; a1.z += wB * vB.z; a1.w += wB * vB.w;
    }
    for (int e = 32; e < cnt; e += 4) {
        int ee = e + q;
        bool ok = ee < cnt;
        int2 pk = ok ? cs[ee] : make_int2(0, 0);
        float wgt = __int_as_float(pk.y);
        float4 v = S4[(size_t)pk.x * 8 + l];
        a0.x += wgt * v.x; a0.y += wgt * v.y; a0.z += wgt * v.z; a0.w += wgt * v.w;
    }
    float4 acc = make_float4(a0.x + a1.x, a0.y + a1.y, a0.z + a1.z, a0.w + a1.w);
#pragma unroll
    for (int m = 8; m <= 16; m <<= 1) {
        acc.x += __shfl_xor_sync(full, acc.x, m);
        acc.y += __shfl_xor_sync(full, acc.y, m);
        acc.z += __shfl_xor_sync(full, acc.z, m);
        acc.w += __shfl_xor_sync(full, acc.w, m);
    }
    if (lane < 8) {
        float4 b = reinterpret_cast<const float4*>(b2)[lane];
        acc.x = acc.x * ai + b.x;
        acc.y = acc.y * ai + b.y;
        acc.z = acc.z * ai + b.z;
        acc.w = acc.w * ai + b.w;
        reinterpret_cast<float4*>(Out)[(size_t)wp * 8 + lane] = acc;
    }
}

// ---------------- launch ----------------
extern "C" void kernel_launch(void* const* d_in, const int* in_sizes, int n_in,
                              void* d_out, int out_size) {
    const float* feat = (const float*)d_in[0];
    const int* esrc = (const int*)d_in[1];
    const int* edst = (const int*)d_in[2];
    const float* ew = (const float*)d_in[3];
    const float* Wih = (const float*)d_in[4];
    const float* Whh = (const float*)d_in[5];
    const float* bih = (const float*)d_in[6];
    const float* bhh = (const float*)d_in[7];
    const float* W0 = (const float*)d_in[8];
    const float* b0 = (const float*)d_in[9];
    const float* W1 = (const float*)d_in[10];
    const float* b1 = (const float*)d_in[11];
    const float* W2 = (const float*)d_in[12];
    const float* b2 = (const float*)d_in[13];
    float* out = (float*)d_out;

    int n = in_sizes[0] / 8;
    int E = in_sizes[1];

    const int TB = 256;
    int aggBlocks = (n * 32 + TB - 1) / TB;
    int thrBlocks = (n + 255) / 256;
    int nbN = (n + 255) / 256;
    int edgeThreads = (E + 3) / 4;
    int nbE = (edgeThreads + TB - 1) / TB;

    // launches: pre(0), lstm(1), agg24(2), gemm0(3 <- ncu), agg64(4), gemm12(5), final(6)
    k_pre<<<nbN + nbE, TB>>>(feat, Wih, bih, bhh, esrc, edst, ew, n, E, nbN);
    k_lstm<<<(n + 127) / 128, 128>>>(Whh, bih, bhh, n);
    k_agg24<<<aggBlocks, TB>>>(n);
    k_gemm0<<<thrBlocks, TB>>>(W0, b0, n);
    k_agg64<<<aggBlocks, TB>>>(n);
    k_gemm12<<<thrBlocks, TB>>>(W1, b1, W2, n);
    k_final<<<aggBlocks, TB>>>(b2, out, n);
}